// round 3
// baseline (speedup 1.0000x reference)
#include <cuda_runtime.h>
#include <math.h>

#define NB 4096
#define NI 256
#define NO 256
#define NG 32

constexpr int OT  = 16;   // o-tile per block in main kernel
constexpr int BCH = 4;    // b-chunks per group
constexpr int N_MS_BLOCKS = (NG * NO * NI / 4) / 256;  // 2048
constexpr int N_XS_BLOCKS = (NB * NI / 4) / 256;       // 1024
constexpr int PREP_BLOCKS = N_MS_BLOCKS + N_XS_BLOCKS + 1;
constexpr int N_GW_BLOCKS = (NO * NI / 4) / 256;       // 64

// ---------------- scratch (device globals; no allocation) ----------------
__device__ float d_xs[NB * NI];          // x * ard_scale
__device__ float d_M[NG * NO * NI];      // gw_mu + gw_sigma*rw_mu[g]
__device__ float d_S[NG * NO * NI];      // gw_sigma*rw_sigma[g]
__device__ float d_gws[NO * NI];         // softplus(gw_rho)
__device__ float d_biasM[NG * NO];
__device__ float d_biasS[NG * NO];
__device__ int   d_perm[NB];
__device__ int   d_goff[NG + 1];
__device__ float d_kl0;
__device__ float d_pms[N_MS_BLOCKS];
__device__ float d_pgw[N_GW_BLOCKS];

// precise softplus (used only where cheap)
__device__ __forceinline__ float sp(float x) {
    return fmaxf(x, 0.0f) + log1pf(expf(-fabsf(x)));
}
// fast softplus via MUFU (rel err ~1e-5, fine vs 1e-3 tolerance)
__device__ __forceinline__ float spf(float x) {
    return fmaxf(x, 0.0f) + __logf(1.0f + __expf(-fabsf(x)));
}

// shfl-based block reduce for 256 threads; result valid in thread 0
__device__ __forceinline__ float blockReduce256s(float v) {
    __shared__ float red[8];
    #pragma unroll
    for (int s = 16; s; s >>= 1) v += __shfl_down_sync(0xffffffffu, v, s);
    if ((threadIdx.x & 31) == 0) red[threadIdx.x >> 5] = v;
    __syncthreads();
    if (threadIdx.x < 8) {
        v = red[threadIdx.x];
        #pragma unroll
        for (int s = 4; s; s >>= 1) v += __shfl_down_sync(0xffu, v, s);
    }
    return v;
}

// ---------------- k_gws: gw_sigma table + gw KL partials (64 blocks) ----------------
__global__ void __launch_bounds__(256)
k_gws(const float* __restrict__ gwmu, const float* __restrict__ gwrho) {
    int idx = blockIdx.x * 256 + threadIdx.x;        // float4 index over O*I/4
    float4 gm = ((const float4*)gwmu)[idx];
    float4 gr = ((const float4*)gwrho)[idx];
    float4 gs;
    float kl = 0.0f;
    #pragma unroll
    for (int c = 0; c < 4; c++) {
        float rho = (c == 0) ? gr.x : (c == 1) ? gr.y : (c == 2) ? gr.z : gr.w;
        float mu  = (c == 0) ? gm.x : (c == 1) ? gm.y : (c == 2) ? gm.z : gm.w;
        float s = spf(rho);
        float ls = __logf(s);
        if (c == 0) gs.x = s; else if (c == 1) gs.y = s; else if (c == 2) gs.z = s; else gs.w = s;
        kl += (-ls + (s * s + mu * mu) * 0.5f - 0.5f)                        // group prior
            + (-1.41893853320467f - ls + (ls * ls + s * s) * 0.5f);          // half-normal
    }
    ((float4*)d_gws)[idx] = gs;
    float tot = blockReduce256s(kl);
    if (threadIdx.x == 0) d_pgw[blockIdx.x] = tot;
}

// ---------------- k_prep: M/S tables + xs + small/bucket ----------------
__global__ void __launch_bounds__(256)
k_prep(const float* __restrict__ x,
       const float* __restrict__ gwmu,
       const float* __restrict__ gbmu, const float* __restrict__ gbrho,
       const float* __restrict__ rwmu, const float* __restrict__ rwrho,
       const float* __restrict__ rbmu, const float* __restrict__ rbrho,
       const float* __restrict__ alpha, const float* __restrict__ beta,
       const int* __restrict__ gids) {
    int bid = blockIdx.x;
    int tid = threadIdx.x;

    if (bid < N_MS_BLOCKS) {
        // ---- M/S tables + rw KL partials ----
        int idx = bid * 256 + tid;              // float4 index over G*O*I/4
        int i4 = idx & (NI / 4 - 1);
        int go = idx >> 6;
        int o  = go & (NO - 1);
        int goi4 = o * (NI / 4) + i4;

        float4 rm = ((const float4*)rwmu)[idx];
        float4 rr = ((const float4*)rwrho)[idx];
        float4 gm = ((const float4*)gwmu)[goi4];
        float4 gs = ((const float4*)d_gws)[goi4];

        float4 Mv, Sv;
        float kl = 0.0f;
        {
            float rs = spf(rr.x); float ls = __logf(rs);
            Sv.x = gs.x * rs; Mv.x = fmaf(gs.x, rm.x, gm.x);
            kl += -1.41893853320467f - ls + (rs * rs + rm.x * rm.x) * 0.5f;
        }
        {
            float rs = spf(rr.y); float ls = __logf(rs);
            Sv.y = gs.y * rs; Mv.y = fmaf(gs.y, rm.y, gm.y);
            kl += -1.41893853320467f - ls + (rs * rs + rm.y * rm.y) * 0.5f;
        }
        {
            float rs = spf(rr.z); float ls = __logf(rs);
            Sv.z = gs.z * rs; Mv.z = fmaf(gs.z, rm.z, gm.z);
            kl += -1.41893853320467f - ls + (rs * rs + rm.z * rm.z) * 0.5f;
        }
        {
            float rs = spf(rr.w); float ls = __logf(rs);
            Sv.w = gs.w * rs; Mv.w = fmaf(gs.w, rm.w, gm.w);
            kl += -1.41893853320467f - ls + (rs * rs + rm.w * rm.w) * 0.5f;
        }
        ((float4*)d_M)[idx] = Mv;
        ((float4*)d_S)[idx] = Sv;

        float tot = blockReduce256s(kl);
        if (tid == 0) d_pms[bid] = tot;

    } else if (bid < N_MS_BLOCKS + N_XS_BLOCKS) {
        // ---- xs = x * sp(alpha)*sp(beta), ard inline (precise sp: tiny count) ----
        int j = (bid - N_MS_BLOCKS) * 256 + tid;   // float4 index over B*I/4
        int i4 = j & (NI / 4 - 1);
        float4 xv = ((const float4*)x)[j];
        float4 av = ((const float4*)alpha)[i4];
        float4 bv = ((const float4*)beta)[i4];
        float4 r;
        r.x = xv.x * (sp(av.x) * sp(bv.x));
        r.y = xv.y * (sp(av.y) * sp(bv.y));
        r.z = xv.z * (sp(av.z) * sp(bv.z));
        r.w = xv.w * (sp(av.w) * sp(bv.w));
        ((float4*)d_xs)[j] = r;

    } else {
        // ---- small KL + bias tables + bucketing ----
        __shared__ int cnt[NG];
        __shared__ int off[NG];
        float kl = 0.0f;

        // sp(alpha).sum + sp(beta).sum (NI == 256 == blockDim); precise
        kl += sp(alpha[tid]) + sp(beta[tid]);

        // gb half-normal KL (NO == 256); precise
        float s  = sp(gbrho[tid]);
        float ls = logf(s);
        kl += -1.41893853320467f - ls + (ls * ls + s * s) * 0.5f;

        // bias tables
        for (int k = tid; k < NG * NO; k += 256) {
            int o = k & (NO - 1);
            float gs = sp(gbrho[o]);
            d_biasM[k] = fmaf(gs, rbmu[k], gbmu[o]);
            d_biasS[k] = gs * sp(rbrho[k]);
        }

        float tot = blockReduce256s(kl);
        if (tid == 0) d_kl0 = tot;

        // bucket pass 1: counts
        if (tid < NG) cnt[tid] = 0;
        __syncthreads();
        for (int b = tid; b < NB; b += 256)
            atomicAdd(&cnt[gids[b]], 1);
        __syncthreads();
        if (tid == 0) {
            int acc = 0;
            for (int g = 0; g < NG; g++) {
                off[g] = acc; d_goff[g] = acc; acc += cnt[g];
            }
            d_goff[NG] = acc;
        }
        __syncthreads();
        if (tid < NG) cnt[tid] = 0;
        __syncthreads();
        // bucket pass 2: scatter (rank order irrelevant to results)
        for (int b = tid; b < NB; b += 256) {
            int g = gids[b];
            int r = atomicAdd(&cnt[g], 1);
            d_perm[off[g] + r] = b;
        }
    }
}

// ---------------- k_main: streamed eps_w GEMV, warp-per-(b, o-tile) ----------------
__global__ void __launch_bounds__(256, 6)
k_main(const float* __restrict__ epsw, const float* __restrict__ epsb,
       float* __restrict__ out, float* __restrict__ klout) {
    __shared__ float sS[OT * NI];
    __shared__ float sM[OT * NI];
    __shared__ float sbM[OT];
    __shared__ float sbS[OT];
    __shared__ float stage[8][OT];

    int tid = threadIdx.x;
    int g   = blockIdx.y;
    int ob  = blockIdx.x * OT;

    // deterministic fixed-structure KL finalize (block (0,0,0) only)
    if (blockIdx.x == 0 && blockIdx.y == 0 && blockIdx.z == 0 && tid < 32) {
        float v = (tid == 0) ? d_kl0 : 0.0f;
        for (int k = tid; k < N_MS_BLOCKS; k += 32) v += d_pms[k];
        for (int k = tid; k < N_GW_BLOCKS; k += 32) v += d_pgw[k];
        #pragma unroll
        for (int o2 = 16; o2; o2 >>= 1) v += __shfl_down_sync(0xffffffffu, v, o2);
        if (tid == 0) *klout = v;
    }

    // stage M/S tile for (g, o-tile) in SMEM
    const float4* Sg = (const float4*)(d_S + ((size_t)g * NO + ob) * NI);
    const float4* Mg = (const float4*)(d_M + ((size_t)g * NO + ob) * NI);
    #pragma unroll 2
    for (int k = tid; k < OT * NI / 4; k += 256) {
        ((float4*)sS)[k] = Sg[k];
        ((float4*)sM)[k] = Mg[k];
    }
    if (tid < OT) {
        sbM[tid] = d_biasM[g * NO + ob + tid];
        sbS[tid] = d_biasS[g * NO + ob + tid];
    }
    __syncthreads();

    int start = d_goff[g];
    int cnt   = d_goff[g + 1] - start;
    int z     = blockIdx.z;
    int c0 = start + (cnt * z) / BCH;
    int c1 = start + (cnt * (z + 1)) / BCH;

    int warp = tid >> 5, lane = tid & 31;

    for (int si = c0 + warp; si < c1; si += 8) {
        int b = d_perm[si];

        // xs row held in registers for all 16 outputs
        const float4* xp = (const float4*)d_xs + (size_t)b * (NI / 4);
        float4 x0 = xp[lane];
        float4 x1 = xp[lane + 32];

        const float4* ep = (const float4*)epsw + ((size_t)b * NO + ob) * (NI / 4);

        #pragma unroll 8
        for (int ol = 0; ol < OT; ol++) {
            float4 e0 = ep[ol * (NI / 4) + lane];
            float4 e1 = ep[ol * (NI / 4) + lane + 32];

            const float4* Sp = (const float4*)(sS + ol * NI);
            const float4* Mp = (const float4*)(sM + ol * NI);
            float4 s0 = Sp[lane], m0 = Mp[lane];
            float4 s1 = Sp[lane + 32], m1 = Mp[lane + 32];

            float acc;
            acc = fmaf(fmaf(s0.x, e0.x, m0.x), x0.x, 0.0f);
            acc = fmaf(fmaf(s0.y, e0.y, m0.y), x0.y, acc);
            acc = fmaf(fmaf(s0.z, e0.z, m0.z), x0.z, acc);
            acc = fmaf(fmaf(s0.w, e0.w, m0.w), x0.w, acc);
            acc = fmaf(fmaf(s1.x, e1.x, m1.x), x1.x, acc);
            acc = fmaf(fmaf(s1.y, e1.y, m1.y), x1.y, acc);
            acc = fmaf(fmaf(s1.z, e1.z, m1.z), x1.z, acc);
            acc = fmaf(fmaf(s1.w, e1.w, m1.w), x1.w, acc);

            #pragma unroll
            for (int o2 = 16; o2; o2 >>= 1)
                acc += __shfl_down_sync(0xffffffffu, acc, o2);
            if (lane == 0) stage[warp][ol] = acc;
        }
        __syncwarp();

        // coalesced epilogue: 16-float store + 16-float epsb load
        if (lane < OT) {
            float bo = fmaf(sbS[lane], epsb[(size_t)b * NO + ob + lane], sbM[lane]);
            out[(size_t)b * NO + ob + lane] = stage[warp][lane] + bo;
        }
        __syncwarp();
    }
}

// ---------------- launch ----------------
extern "C" void kernel_launch(void* const* d_in, const int* in_sizes, int n_in,
                              void* d_out, int out_size) {
    const float* x     = (const float*)d_in[0];
    const float* gwmu  = (const float*)d_in[1];
    const float* gwrho = (const float*)d_in[2];
    const float* gbmu  = (const float*)d_in[3];
    const float* gbrho = (const float*)d_in[4];
    const float* rwmu  = (const float*)d_in[5];
    const float* rwrho = (const float*)d_in[6];
    const float* rbmu  = (const float*)d_in[7];
    const float* rbrho = (const float*)d_in[8];
    const float* alpha = (const float*)d_in[9];
    const float* beta  = (const float*)d_in[10];
    const float* epsw  = (const float*)d_in[11];
    const float* epsb  = (const float*)d_in[12];
    const int*   gids  = (const int*)d_in[13];

    float* out   = (float*)d_out;
    float* klout = out + (out_size - 1);

    k_gws<<<N_GW_BLOCKS, 256>>>(gwmu, gwrho);
    k_prep<<<PREP_BLOCKS, 256>>>(x, gwmu, gbmu, gbrho,
                                 rwmu, rwrho, rbmu, rbrho, alpha, beta, gids);

    dim3 grid(NO / OT, NG, BCH);
    k_main<<<grid, 256>>>(epsw, epsb, out, klout);
}

// round 4
// speedup vs baseline: 1.1874x; 1.1874x over previous
#include <cuda_runtime.h>
#include <math.h>

#define NB 4096
#define NI 256
#define NO 256
#define NG 32

constexpr int OT  = 16;   // o-tile per block in main kernel
constexpr int BCH = 4;    // b-chunks per group
constexpr int N_MS_BLOCKS = (NG * NO * NI / 4) / 256;  // 2048
constexpr int N_XS_BLOCKS = (NB * NI / 4) / 256;       // 1024
constexpr int PREP_BLOCKS = N_MS_BLOCKS + N_XS_BLOCKS + 1;

// ---------------- scratch (device globals; no allocation) ----------------
__device__ float d_xs[NB * NI];          // x * ard_scale
__device__ float d_M[NG * NO * NI];      // gw_mu + gw_sigma*rw_mu[g]
__device__ float d_S[NG * NO * NI];      // gw_sigma*rw_sigma[g]
__device__ float d_biasM[NG * NO];
__device__ float d_biasS[NG * NO];
__device__ int   d_perm[NB];
__device__ int   d_goff[NG + 1];
__device__ float d_kl0;
__device__ float d_pms[N_MS_BLOCKS];

// precise softplus (used only on tiny arrays)
__device__ __forceinline__ float sp(float x) {
    return fmaxf(x, 0.0f) + log1pf(expf(-fabsf(x)));
}
// fast softplus via MUFU (rel err ~1e-5 on sigma; tolerance is 1e-3)
__device__ __forceinline__ float spf(float x) {
    return fmaxf(x, 0.0f) + __logf(1.0f + __expf(-fabsf(x)));
}

// shfl-based block reduce for 256 threads; result valid in thread 0
__device__ __forceinline__ float blockReduce256s(float v) {
    __shared__ float red[8];
    #pragma unroll
    for (int s = 16; s; s >>= 1) v += __shfl_down_sync(0xffffffffu, v, s);
    if ((threadIdx.x & 31) == 0) red[threadIdx.x >> 5] = v;
    __syncthreads();
    if (threadIdx.x < 8) {
        v = red[threadIdx.x];
        #pragma unroll
        for (int s = 4; s; s >>= 1) v += __shfl_down_sync(0xffu, v, s);
    }
    return v;
}

// ---------------- k_prep: everything before the big stream ----------------
// blocks [0, 2048)    : M/S tables + rw KL (+ gw KL on blocks < 64)
// blocks [2048, 3072) : xs = x * ard_scale (ard inline)
// block  3072         : bias tables, small KL terms, group bucketing
__global__ void __launch_bounds__(256)
k_prep(const float* __restrict__ x,
       const float* __restrict__ gwmu, const float* __restrict__ gwrho,
       const float* __restrict__ gbmu, const float* __restrict__ gbrho,
       const float* __restrict__ rwmu, const float* __restrict__ rwrho,
       const float* __restrict__ rbmu, const float* __restrict__ rbrho,
       const float* __restrict__ alpha, const float* __restrict__ beta,
       const int* __restrict__ gids) {
    int bid = blockIdx.x;
    int tid = threadIdx.x;

    if (bid < N_MS_BLOCKS) {
        // ---- M/S tables + KL partials ----
        int idx = bid * 256 + tid;              // float4 index over G*O*I/4
        int i4 = idx & (NI / 4 - 1);
        int go = idx >> 6;
        int o  = go & (NO - 1);
        int goi4 = o * (NI / 4) + i4;

        float4 rm = ((const float4*)rwmu)[idx];
        float4 rr = ((const float4*)rwrho)[idx];
        float4 gm = ((const float4*)gwmu)[goi4];
        float4 gr = ((const float4*)gwrho)[goi4];

        float4 Mv, Sv, gsv;
        float kl = 0.0f;
        {
            float gs = spf(gr.x); gsv.x = gs;
            float rs = spf(rr.x); float ls = __logf(rs);
            Sv.x = gs * rs; Mv.x = fmaf(gs, rm.x, gm.x);
            kl += -1.41893853320467f - ls + (rs * rs + rm.x * rm.x) * 0.5f;
        }
        {
            float gs = spf(gr.y); gsv.y = gs;
            float rs = spf(rr.y); float ls = __logf(rs);
            Sv.y = gs * rs; Mv.y = fmaf(gs, rm.y, gm.y);
            kl += -1.41893853320467f - ls + (rs * rs + rm.y * rm.y) * 0.5f;
        }
        {
            float gs = spf(gr.z); gsv.z = gs;
            float rs = spf(rr.z); float ls = __logf(rs);
            Sv.z = gs * rs; Mv.z = fmaf(gs, rm.z, gm.z);
            kl += -1.41893853320467f - ls + (rs * rs + rm.z * rm.z) * 0.5f;
        }
        {
            float gs = spf(gr.w); gsv.w = gs;
            float rs = spf(rr.w); float ls = __logf(rs);
            Sv.w = gs * rs; Mv.w = fmaf(gs, rm.w, gm.w);
            kl += -1.41893853320467f - ls + (rs * rs + rm.w * rm.w) * 0.5f;
        }
        ((float4*)d_M)[idx] = Mv;
        ((float4*)d_S)[idx] = Sv;

        // gw KL terms exactly once: blocks covering g==0 (idx < NO*NI/4)
        if (idx < NO * NI / 4) {
            #pragma unroll
            for (int c = 0; c < 4; c++) {
                float s  = (c == 0) ? gsv.x : (c == 1) ? gsv.y : (c == 2) ? gsv.z : gsv.w;
                float mu = (c == 0) ? gm.x  : (c == 1) ? gm.y  : (c == 2) ? gm.z  : gm.w;
                float ls = __logf(s);
                kl += (-ls + (s * s + mu * mu) * 0.5f - 0.5f)                  // group prior
                    + (-1.41893853320467f - ls + (ls * ls + s * s) * 0.5f);    // half-normal
            }
        }
        float tot = blockReduce256s(kl);
        if (tid == 0) d_pms[bid] = tot;

    } else if (bid < N_MS_BLOCKS + N_XS_BLOCKS) {
        // ---- xs = x * sp(alpha)*sp(beta), ard inline ----
        int j = (bid - N_MS_BLOCKS) * 256 + tid;   // float4 index over B*I/4
        int i4 = j & (NI / 4 - 1);
        float4 xv = ((const float4*)x)[j];
        float4 av = ((const float4*)alpha)[i4];
        float4 bv = ((const float4*)beta)[i4];
        float4 r;
        r.x = xv.x * (sp(av.x) * sp(bv.x));
        r.y = xv.y * (sp(av.y) * sp(bv.y));
        r.z = xv.z * (sp(av.z) * sp(bv.z));
        r.w = xv.w * (sp(av.w) * sp(bv.w));
        ((float4*)d_xs)[j] = r;

    } else {
        // ---- small KL + bias tables + bucketing ----
        __shared__ int cnt[NG];
        __shared__ int off[NG];
        float kl = 0.0f;

        // sp(alpha).sum + sp(beta).sum (NI == 256 == blockDim); precise
        kl += sp(alpha[tid]) + sp(beta[tid]);

        // gb half-normal KL (NO == 256); precise
        float s  = sp(gbrho[tid]);
        float ls = logf(s);
        kl += -1.41893853320467f - ls + (ls * ls + s * s) * 0.5f;

        // bias tables
        for (int k = tid; k < NG * NO; k += 256) {
            int o = k & (NO - 1);
            float gs = sp(gbrho[o]);
            d_biasM[k] = fmaf(gs, rbmu[k], gbmu[o]);
            d_biasS[k] = gs * sp(rbrho[k]);
        }

        float tot = blockReduce256s(kl);
        if (tid == 0) d_kl0 = tot;

        // bucket pass 1: counts
        if (tid < NG) cnt[tid] = 0;
        __syncthreads();
        for (int b = tid; b < NB; b += 256)
            atomicAdd(&cnt[gids[b]], 1);
        __syncthreads();
        if (tid == 0) {
            int acc = 0;
            for (int g = 0; g < NG; g++) {
                off[g] = acc; d_goff[g] = acc; acc += cnt[g];
            }
            d_goff[NG] = acc;
        }
        __syncthreads();
        if (tid < NG) cnt[tid] = 0;
        __syncthreads();
        // bucket pass 2: scatter (rank order irrelevant to results)
        for (int b = tid; b < NB; b += 256) {
            int g = gids[b];
            int r = atomicAdd(&cnt[g], 1);
            d_perm[off[g] + r] = b;
        }
    }
}

// ---------------- k_main: streamed eps_w GEMV, warp-per-(b, o-tile) ----------------
__global__ void __launch_bounds__(256, 4)
k_main(const float* __restrict__ epsw, const float* __restrict__ epsb,
       float* __restrict__ out, float* __restrict__ klout) {
    __shared__ float sS[OT * NI];
    __shared__ float sM[OT * NI];
    __shared__ float sbM[OT];
    __shared__ float sbS[OT];
    __shared__ float stage[8][OT];

    int tid = threadIdx.x;
    int g   = blockIdx.y;
    int ob  = blockIdx.x * OT;

    // deterministic fixed-structure KL finalize (block (0,0,0) only)
    if (blockIdx.x == 0 && blockIdx.y == 0 && blockIdx.z == 0 && tid < 32) {
        float v = (tid == 0) ? d_kl0 : 0.0f;
        for (int k = tid; k < N_MS_BLOCKS; k += 32) v += d_pms[k];
        #pragma unroll
        for (int o2 = 16; o2; o2 >>= 1) v += __shfl_down_sync(0xffffffffu, v, o2);
        if (tid == 0) *klout = v;
    }

    // stage M/S tile for (g, o-tile) in SMEM
    const float4* Sg = (const float4*)(d_S + ((size_t)g * NO + ob) * NI);
    const float4* Mg = (const float4*)(d_M + ((size_t)g * NO + ob) * NI);
    #pragma unroll 2
    for (int k = tid; k < OT * NI / 4; k += 256) {
        ((float4*)sS)[k] = Sg[k];
        ((float4*)sM)[k] = Mg[k];
    }
    if (tid < OT) {
        sbM[tid] = d_biasM[g * NO + ob + tid];
        sbS[tid] = d_biasS[g * NO + ob + tid];
    }
    __syncthreads();

    int start = d_goff[g];
    int cnt   = d_goff[g + 1] - start;
    int z     = blockIdx.z;
    int c0 = start + (cnt * z) / BCH;
    int c1 = start + (cnt * (z + 1)) / BCH;

    int warp = tid >> 5, lane = tid & 31;

    for (int si = c0 + warp; si < c1; si += 8) {
        int b = d_perm[si];

        // xs row held in registers for all 16 outputs
        const float4* xp = (const float4*)d_xs + (size_t)b * (NI / 4);
        float4 x0 = xp[lane];
        float4 x1 = xp[lane + 32];

        const float4* ep = (const float4*)epsw + ((size_t)b * NO + ob) * (NI / 4);

        #pragma unroll 4
        for (int ol = 0; ol < OT; ol++) {
            float4 e0 = ep[ol * (NI / 4) + lane];
            float4 e1 = ep[ol * (NI / 4) + lane + 32];

            const float4* Sp = (const float4*)(sS + ol * NI);
            const float4* Mp = (const float4*)(sM + ol * NI);
            float4 s0 = Sp[lane], m0 = Mp[lane];
            float4 s1 = Sp[lane + 32], m1 = Mp[lane + 32];

            float acc;
            acc = fmaf(fmaf(s0.x, e0.x, m0.x), x0.x, 0.0f);
            acc = fmaf(fmaf(s0.y, e0.y, m0.y), x0.y, acc);
            acc = fmaf(fmaf(s0.z, e0.z, m0.z), x0.z, acc);
            acc = fmaf(fmaf(s0.w, e0.w, m0.w), x0.w, acc);
            acc = fmaf(fmaf(s1.x, e1.x, m1.x), x1.x, acc);
            acc = fmaf(fmaf(s1.y, e1.y, m1.y), x1.y, acc);
            acc = fmaf(fmaf(s1.z, e1.z, m1.z), x1.z, acc);
            acc = fmaf(fmaf(s1.w, e1.w, m1.w), x1.w, acc);

            #pragma unroll
            for (int o2 = 16; o2; o2 >>= 1)
                acc += __shfl_down_sync(0xffffffffu, acc, o2);
            if (lane == 0) stage[warp][ol] = acc;
        }
        __syncwarp();

        // coalesced epilogue: 16-float store + 16-float epsb load
        if (lane < OT) {
            float bo = fmaf(sbS[lane], epsb[(size_t)b * NO + ob + lane], sbM[lane]);
            out[(size_t)b * NO + ob + lane] = stage[warp][lane] + bo;
        }
        __syncwarp();
    }
}

// ---------------- launch ----------------
extern "C" void kernel_launch(void* const* d_in, const int* in_sizes, int n_in,
                              void* d_out, int out_size) {
    const float* x     = (const float*)d_in[0];
    const float* gwmu  = (const float*)d_in[1];
    const float* gwrho = (const float*)d_in[2];
    const float* gbmu  = (const float*)d_in[3];
    const float* gbrho = (const float*)d_in[4];
    const float* rwmu  = (const float*)d_in[5];
    const float* rwrho = (const float*)d_in[6];
    const float* rbmu  = (const float*)d_in[7];
    const float* rbrho = (const float*)d_in[8];
    const float* alpha = (const float*)d_in[9];
    const float* beta  = (const float*)d_in[10];
    const float* epsw  = (const float*)d_in[11];
    const float* epsb  = (const float*)d_in[12];
    const int*   gids  = (const int*)d_in[13];

    float* out   = (float*)d_out;
    float* klout = out + (out_size - 1);

    k_prep<<<PREP_BLOCKS, 256>>>(x, gwmu, gwrho, gbmu, gbrho,
                                 rwmu, rwrho, rbmu, rbrho, alpha, beta, gids);

    dim3 grid(NO / OT, NG, BCH);
    k_main<<<grid, 256>>>(epsw, epsb, out, klout);
}